// round 3
// baseline (speedup 1.0000x reference)
#include <cuda_runtime.h>
#include <cstdint>

#define R_ROIS 300
#define CCH    512
#define HFDIM  50
#define WFDIM  50
#define POOLK  25088   // 512*7*7
#define NFC    4096
#define NHEAD  128     // padded head output cols (84 loc + 21 score + pad)

// ---------------- scratch (no allocations allowed) ----------------
__device__ __align__(16) float g_pool[R_ROIS * POOLK];       // ~30 MB
__device__ __align__(16) float g_fc6 [R_ROIS * NFC];
__device__ __align__(16) float g_fc7 [R_ROIS * NFC];
__device__ __align__(16) float g_part[4 * R_ROIS * NFC];     // split-K partials (max S=4 for N=4096)
__device__ __align__(16) float g_Whead[NFC * NHEAD];         // packed W_loc|W_score

// ---------------- helpers ----------------
__device__ __forceinline__ float f2tf32(float x) {
    float r;
    asm("cvt.rna.tf32.f32 %0, %1;" : "=f"(r) : "f"(x));
    return r;
}

__device__ __forceinline__ void mma_tf32(float& c0, float& c1, float& c2, float& c3,
                                         uint32_t a0, uint32_t a1, uint32_t a2, uint32_t a3,
                                         uint32_t b0, uint32_t b1) {
    asm volatile(
        "mma.sync.aligned.m16n8k8.row.col.f32.tf32.tf32.f32 "
        "{%0,%1,%2,%3}, {%4,%5,%6,%7}, {%8,%9}, {%0,%1,%2,%3};\n"
        : "+f"(c0), "+f"(c1), "+f"(c2), "+f"(c3)
        : "r"(a0), "r"(a1), "r"(a2), "r"(a3), "r"(b0), "r"(b1));
}

// ---------------- RoI adaptive max pool ----------------
// one block per roi; output layout [r][c*49 + iy*7 + ix] matches reshape(R, C*7*7)
__global__ void roi_pool_kernel(const float* __restrict__ x,
                                const float* __restrict__ rois,
                                float* __restrict__ pool) {
    const int r = blockIdx.x;
    __shared__ int rs[7], re[7], cs[7], ce[7];
    if (threadIdx.x < 7) {
        const int i = threadIdx.x;
        const int y1 = (int)(rois[r * 4 + 0] * 0.0625f);
        const int x1 = (int)(rois[r * 4 + 1] * 0.0625f);
        const int y2 = (int)(rois[r * 4 + 2] * 0.0625f);
        const int x2 = (int)(rois[r * 4 + 3] * 0.0625f);
        const int h = y2 - y1 + 1;
        const int w = x2 - x1 + 1;
        rs[i] = y1 + (i * h) / 7;
        re[i] = y1 + ((i + 1) * h + 6) / 7;
        cs[i] = x1 + (i * w) / 7;
        ce[i] = x1 + ((i + 1) * w + 6) / 7;
    }
    __syncthreads();
    for (int idx = threadIdx.x; idx < CCH * 49; idx += blockDim.x) {
        const int c  = idx / 49;
        const int b  = idx - c * 49;
        const int iy = b / 7;
        const int ix = b - iy * 7;
        const float* fp = x + (size_t)c * (HFDIM * WFDIM);
        float m = -3.402823466e38f;
        const int y0 = rs[iy], y1e = re[iy];
        const int x0 = cs[ix], x1e = ce[ix];
        for (int y = y0; y < y1e; ++y) {
            const float* row = fp + y * WFDIM;
            for (int xx = x0; xx < x1e; ++xx)
                m = fmaxf(m, __ldg(row + xx));
        }
        pool[(size_t)r * POOLK + idx] = m;
    }
}

// ---------------- pack W_loc | W_score into [4096][128] (zero-padded) ----------------
__global__ void pack_head_kernel(const float* __restrict__ Wl,
                                 const float* __restrict__ Ws,
                                 float* __restrict__ Wh) {
    const int idx = blockIdx.x * blockDim.x + threadIdx.x;
    if (idx >= NFC * NHEAD) return;
    const int k = idx >> 7;
    const int j = idx & 127;
    float v = 0.0f;
    if (j < 84)       v = Wl[k * 84 + j];
    else if (j < 105) v = Ws[k * 21 + (j - 84)];
    Wh[idx] = v;
}

// ---------------- tf32 GEMM, split-K into partial slices ----------------
// C layout: Cpart[(z*M + row)*N + col].  BM=128, BN=128, BK=16, 256 threads (2x4 warps).
__global__ void __launch_bounds__(256, 2)
gemm_tf32(const float* __restrict__ A, const float* __restrict__ B,
          float* __restrict__ C, int M, int N, int K, int kChunk) {
    __shared__ float As[2][16][132];   // transposed: As[k][m]
    __shared__ float Bs[2][16][132];   // Bs[k][n]

    const int tid  = threadIdx.x;
    const int lane = tid & 31;
    const int warp = tid >> 5;
    const int wm   = warp >> 2;   // 0..1
    const int wn   = warp & 3;    // 0..3
    const int g    = lane >> 2;   // 0..7
    const int cq   = lane & 3;    // 0..3

    const int mblk  = blockIdx.y * 128;
    const int nblk  = blockIdx.x * 128;
    const int z     = blockIdx.z;
    const int kbase = z * kChunk;
    const int nk    = kChunk >> 4;

    // global load task coords (2 float4s for A, 2 for B per thread per tile)
    const int aM0 = tid >> 2,        aQ = tid & 3;
    const int aM1 = (tid + 256) >> 2;
    const int bK0 = tid >> 5,        bQ = tid & 31;
    const int bK1 = bK0 + 8;

    float acc[4][4][4];
#pragma unroll
    for (int i = 0; i < 4; ++i)
#pragma unroll
        for (int j = 0; j < 4; ++j)
#pragma unroll
            for (int k = 0; k < 4; ++k) acc[i][j][k] = 0.0f;

    float4 av0, av1, bv0, bv1;

    // prologue: fetch tile 0
    {
        const int kg = kbase;
        int gm = mblk + aM0;
        av0 = (gm < M) ? *(const float4*)(A + (size_t)gm * K + kg + aQ * 4)
                       : make_float4(0.f, 0.f, 0.f, 0.f);
        gm = mblk + aM1;
        av1 = (gm < M) ? *(const float4*)(A + (size_t)gm * K + kg + aQ * 4)
                       : make_float4(0.f, 0.f, 0.f, 0.f);
        bv0 = *(const float4*)(B + (size_t)(kg + bK0) * N + nblk + bQ * 4);
        bv1 = *(const float4*)(B + (size_t)(kg + bK1) * N + nblk + bQ * 4);

        As[0][aQ * 4 + 0][aM0] = f2tf32(av0.x);
        As[0][aQ * 4 + 1][aM0] = f2tf32(av0.y);
        As[0][aQ * 4 + 2][aM0] = f2tf32(av0.z);
        As[0][aQ * 4 + 3][aM0] = f2tf32(av0.w);
        As[0][aQ * 4 + 0][aM1] = f2tf32(av1.x);
        As[0][aQ * 4 + 1][aM1] = f2tf32(av1.y);
        As[0][aQ * 4 + 2][aM1] = f2tf32(av1.z);
        As[0][aQ * 4 + 3][aM1] = f2tf32(av1.w);
        Bs[0][bK0][bQ * 4 + 0] = f2tf32(bv0.x);
        Bs[0][bK0][bQ * 4 + 1] = f2tf32(bv0.y);
        Bs[0][bK0][bQ * 4 + 2] = f2tf32(bv0.z);
        Bs[0][bK0][bQ * 4 + 3] = f2tf32(bv0.w);
        Bs[0][bK1][bQ * 4 + 0] = f2tf32(bv1.x);
        Bs[0][bK1][bQ * 4 + 1] = f2tf32(bv1.y);
        Bs[0][bK1][bQ * 4 + 2] = f2tf32(bv1.z);
        Bs[0][bK1][bQ * 4 + 3] = f2tf32(bv1.w);
    }
    __syncthreads();

    for (int kt = 0; kt < nk; ++kt) {
        const int cur = kt & 1;
        const bool more = (kt + 1 < nk);
        if (more) {
            const int kg = kbase + (kt + 1) * 16;
            int gm = mblk + aM0;
            av0 = (gm < M) ? *(const float4*)(A + (size_t)gm * K + kg + aQ * 4)
                           : make_float4(0.f, 0.f, 0.f, 0.f);
            gm = mblk + aM1;
            av1 = (gm < M) ? *(const float4*)(A + (size_t)gm * K + kg + aQ * 4)
                           : make_float4(0.f, 0.f, 0.f, 0.f);
            bv0 = *(const float4*)(B + (size_t)(kg + bK0) * N + nblk + bQ * 4);
            bv1 = *(const float4*)(B + (size_t)(kg + bK1) * N + nblk + bQ * 4);
        }

#pragma unroll
        for (int ks = 0; ks < 2; ++ks) {
            const int kk = ks * 8;
            uint32_t af[4][4];
#pragma unroll
            for (int tm = 0; tm < 4; ++tm) {
                const int row0 = wm * 64 + tm * 16 + g;
                af[tm][0] = __float_as_uint(As[cur][kk + cq    ][row0    ]);
                af[tm][1] = __float_as_uint(As[cur][kk + cq    ][row0 + 8]);
                af[tm][2] = __float_as_uint(As[cur][kk + cq + 4][row0    ]);
                af[tm][3] = __float_as_uint(As[cur][kk + cq + 4][row0 + 8]);
            }
            uint32_t bf[4][2];
#pragma unroll
            for (int tn = 0; tn < 4; ++tn) {
                const int col = wn * 32 + tn * 8 + g;
                bf[tn][0] = __float_as_uint(Bs[cur][kk + cq    ][col]);
                bf[tn][1] = __float_as_uint(Bs[cur][kk + cq + 4][col]);
            }
#pragma unroll
            for (int tm = 0; tm < 4; ++tm)
#pragma unroll
                for (int tn = 0; tn < 4; ++tn)
                    mma_tf32(acc[tm][tn][0], acc[tm][tn][1], acc[tm][tn][2], acc[tm][tn][3],
                             af[tm][0], af[tm][1], af[tm][2], af[tm][3],
                             bf[tn][0], bf[tn][1]);
        }

        if (more) {
            const int nb = cur ^ 1;
            As[nb][aQ * 4 + 0][aM0] = f2tf32(av0.x);
            As[nb][aQ * 4 + 1][aM0] = f2tf32(av0.y);
            As[nb][aQ * 4 + 2][aM0] = f2tf32(av0.z);
            As[nb][aQ * 4 + 3][aM0] = f2tf32(av0.w);
            As[nb][aQ * 4 + 0][aM1] = f2tf32(av1.x);
            As[nb][aQ * 4 + 1][aM1] = f2tf32(av1.y);
            As[nb][aQ * 4 + 2][aM1] = f2tf32(av1.z);
            As[nb][aQ * 4 + 3][aM1] = f2tf32(av1.w);
            Bs[nb][bK0][bQ * 4 + 0] = f2tf32(bv0.x);
            Bs[nb][bK0][bQ * 4 + 1] = f2tf32(bv0.y);
            Bs[nb][bK0][bQ * 4 + 2] = f2tf32(bv0.z);
            Bs[nb][bK0][bQ * 4 + 3] = f2tf32(bv0.w);
            Bs[nb][bK1][bQ * 4 + 0] = f2tf32(bv1.x);
            Bs[nb][bK1][bQ * 4 + 1] = f2tf32(bv1.y);
            Bs[nb][bK1][bQ * 4 + 2] = f2tf32(bv1.z);
            Bs[nb][bK1][bQ * 4 + 3] = f2tf32(bv1.w);
        }
        __syncthreads();
    }

    // write split-K partial slice
    const size_t zbase = (size_t)z * M;
#pragma unroll
    for (int tm = 0; tm < 4; ++tm) {
#pragma unroll
        for (int tn = 0; tn < 4; ++tn) {
            const int row = mblk + wm * 64 + tm * 16 + g;
            const int col = nblk + wn * 32 + tn * 8 + cq * 2;
            if (row < M) {
                C[(zbase + row) * N + col    ] = acc[tm][tn][0];
                C[(zbase + row) * N + col + 1] = acc[tm][tn][1];
            }
            if (row + 8 < M) {
                C[(zbase + row + 8) * N + col    ] = acc[tm][tn][2];
                C[(zbase + row + 8) * N + col + 1] = acc[tm][tn][3];
            }
        }
    }
}

// ---------------- split-K reduce + bias + relu ----------------
__global__ void epi_relu_kernel(const float* __restrict__ part,
                                const float* __restrict__ bias,
                                float* __restrict__ out, int MN, int N, int S) {
    const int idx = blockIdx.x * blockDim.x + threadIdx.x;
    if (idx >= MN) return;
    float v = bias[idx % N];
    for (int s = 0; s < S; ++s) v += part[(size_t)s * MN + idx];
    out[idx] = fmaxf(v, 0.0f);
}

// ---------------- head epilogue: reduce + bias, split into loc/score ----------------
__global__ void epi_head_kernel(const float* __restrict__ part,
                                const float* __restrict__ b_loc,
                                const float* __restrict__ b_score,
                                float* __restrict__ out, int S) {
    const int idx = blockIdx.x * blockDim.x + threadIdx.x;
    if (idx >= R_ROIS * 105) return;
    const int r = idx / 105;
    const int j = idx - r * 105;
    float v = 0.0f;
    for (int s = 0; s < S; ++s)
        v += part[((size_t)s * R_ROIS + r) * NHEAD + j];
    if (j < 84) out[r * 84 + j] = v + b_loc[j];
    else        out[R_ROIS * 84 + r * 21 + (j - 84)] = v + b_score[j - 84];
}

// ---------------- launch ----------------
extern "C" void kernel_launch(void* const* d_in, const int* in_sizes, int n_in,
                              void* d_out, int out_size) {
    const float* x    = (const float*)d_in[0];
    const float* rois = (const float*)d_in[1];
    const float* W6   = (const float*)d_in[2];
    const float* b6   = (const float*)d_in[3];
    const float* W7   = (const float*)d_in[4];
    const float* b7   = (const float*)d_in[5];
    const float* Wl   = (const float*)d_in[6];
    const float* bl   = (const float*)d_in[7];
    const float* Wsc  = (const float*)d_in[8];
    const float* bsc  = (const float*)d_in[9];
    float* out = (float*)d_out;

    float *pool, *fc6, *fc7, *part, *wh;
    cudaGetSymbolAddress((void**)&pool, g_pool);
    cudaGetSymbolAddress((void**)&fc6,  g_fc6);
    cudaGetSymbolAddress((void**)&fc7,  g_fc7);
    cudaGetSymbolAddress((void**)&part, g_part);
    cudaGetSymbolAddress((void**)&wh,   g_Whead);

    roi_pool_kernel<<<R_ROIS, 256>>>(x, rois, pool);
    pack_head_kernel<<<(NFC * NHEAD + 255) / 256, 256>>>(Wl, Wsc, wh);

    // fc6: M=300, N=4096, K=25088, split-K=4 (kChunk=6272)
    gemm_tf32<<<dim3(32, 3, 4), 256>>>(pool, W6, part, R_ROIS, NFC, POOLK, 6272);
    epi_relu_kernel<<<(R_ROIS * NFC + 255) / 256, 256>>>(part, b6, fc6, R_ROIS * NFC, NFC, 4);

    // fc7: M=300, N=4096, K=4096, split-K=2 (kChunk=2048)
    gemm_tf32<<<dim3(32, 3, 2), 256>>>(fc6, W7, part, R_ROIS, NFC, NFC, 2048);
    epi_relu_kernel<<<(R_ROIS * NFC + 255) / 256, 256>>>(part, b7, fc7, R_ROIS * NFC, NFC, 2);

    // heads: M=300, N=128 (packed), K=4096, split-K=8 (kChunk=512)
    gemm_tf32<<<dim3(1, 3, 8), 256>>>(fc7, wh, part, R_ROIS, NHEAD, NFC, 512);
    epi_head_kernel<<<(R_ROIS * 105 + 255) / 256, 256>>>(part, bl, bsc, out, 8);
}

// round 5
// speedup vs baseline: 1.2173x; 1.2173x over previous
#include <cuda_runtime.h>
#include <cstdint>

#define R_ROIS 300
#define CCH    512
#define HFDIM  50
#define WFDIM  50
#define POOLK  25088   // 512*7*7
#define NFC    4096
#define NHEAD  128     // padded head output cols (84 loc + 21 score + pad)

// GEMM tiling
#define STAGES 4
#define ASTR   20                 // A smem row stride (floats): 16 data + 4 pad
#define BSTR   136                // B smem row stride (floats): 128 data + 8 pad
#define ASZ    (128 * ASTR)       // 2560 floats / stage
#define BSZ    (16 * BSTR)        // 2176 floats / stage
#define STAGE_F (ASZ + BSZ)       // 4736 floats
#define SMEM_BYTES (STAGES * STAGE_F * 4)   // 75776 B

// ---------------- scratch (no allocations allowed) ----------------
__device__ __align__(16) float g_pool[R_ROIS * POOLK];
__device__ __align__(16) float g_fc6 [R_ROIS * NFC];
__device__ __align__(16) float g_fc7 [R_ROIS * NFC];
__device__ __align__(16) float g_part[4 * R_ROIS * NFC];
__device__ __align__(16) float g_Whead[NFC * NHEAD];

// ---------------- helpers ----------------
__device__ __forceinline__ uint32_t f2tf32u(float x) {
    uint32_t r;
    asm("cvt.rna.tf32.f32 %0, %1;" : "=r"(r) : "f"(x));
    return r;
}

__device__ __forceinline__ void mma_tf32(float& c0, float& c1, float& c2, float& c3,
                                         uint32_t a0, uint32_t a1, uint32_t a2, uint32_t a3,
                                         uint32_t b0, uint32_t b1) {
    asm volatile(
        "mma.sync.aligned.m16n8k8.row.col.f32.tf32.tf32.f32 "
        "{%0,%1,%2,%3}, {%4,%5,%6,%7}, {%8,%9}, {%0,%1,%2,%3};\n"
        : "+f"(c0), "+f"(c1), "+f"(c2), "+f"(c3)
        : "r"(a0), "r"(a1), "r"(a2), "r"(a3), "r"(b0), "r"(b1));
}

__device__ __forceinline__ void cp_async16(uint32_t smem, const void* gmem, bool full) {
    int sz = full ? 16 : 0;
    asm volatile("cp.async.cg.shared.global [%0], [%1], 16, %2;\n"
                 :: "r"(smem), "l"(gmem), "r"(sz));
}
__device__ __forceinline__ void cp_commit() {
    asm volatile("cp.async.commit_group;\n" ::: "memory");
}
template<int N>
__device__ __forceinline__ void cp_wait() {
    asm volatile("cp.async.wait_group %0;\n" :: "n"(N) : "memory");
}

// ---------------- RoI adaptive max pool ----------------
__global__ void roi_pool_kernel(const float* __restrict__ x,
                                const float* __restrict__ rois,
                                float* __restrict__ pool) {
    const int r = blockIdx.x;
    __shared__ int rs[7], re[7], cs[7], ce[7];
    if (threadIdx.x < 7) {
        const int i = threadIdx.x;
        const int y1 = (int)(rois[r * 4 + 0] * 0.0625f);
        const int x1 = (int)(rois[r * 4 + 1] * 0.0625f);
        const int y2 = (int)(rois[r * 4 + 2] * 0.0625f);
        const int x2 = (int)(rois[r * 4 + 3] * 0.0625f);
        const int h = y2 - y1 + 1;
        const int w = x2 - x1 + 1;
        rs[i] = y1 + (i * h) / 7;
        re[i] = y1 + ((i + 1) * h + 6) / 7;
        cs[i] = x1 + (i * w) / 7;
        ce[i] = x1 + ((i + 1) * w + 6) / 7;
    }
    __syncthreads();
    for (int idx = threadIdx.x; idx < CCH * 49; idx += blockDim.x) {
        const int c  = idx / 49;
        const int b  = idx - c * 49;
        const int iy = b / 7;
        const int ix = b - iy * 7;
        const float* fp = x + (size_t)c * (HFDIM * WFDIM);
        float m = -3.402823466e38f;
        const int y0 = rs[iy], y1e = re[iy];
        const int x0 = cs[ix], x1e = ce[ix];
        for (int y = y0; y < y1e; ++y) {
            const float* row = fp + y * WFDIM;
            for (int xx = x0; xx < x1e; ++xx)
                m = fmaxf(m, __ldg(row + xx));
        }
        pool[(size_t)r * POOLK + idx] = m;
    }
}

// ---------------- pack W_loc | W_score into [4096][128] ----------------
__global__ void pack_head_kernel(const float* __restrict__ Wl,
                                 const float* __restrict__ Ws,
                                 float* __restrict__ Wh) {
    const int idx = blockIdx.x * blockDim.x + threadIdx.x;
    if (idx >= NFC * NHEAD) return;
    const int k = idx >> 7;
    const int j = idx & 127;
    float v = 0.0f;
    if (j < 84)       v = Wl[k * 84 + j];
    else if (j < 105) v = Ws[k * 21 + (j - 84)];
    Wh[idx] = v;
}

// ---------------- tf32 GEMM, cp.async 4-stage pipeline, split-K ----------------
// C layout: Cpart[(z*M + row)*N + col].  BM=128, BN=128, BK=16, 256 threads.
__global__ void __launch_bounds__(256, 2)
gemm_tf32(const float* __restrict__ A, const float* __restrict__ B,
          float* __restrict__ C, int M, int N, int K, int kChunk) {
    extern __shared__ float smem[];

    const int tid  = threadIdx.x;
    const int lane = tid & 31;
    const int warp = tid >> 5;
    const int wm   = warp >> 2;   // 0..1
    const int wn   = warp & 3;    // 0..3
    const int g    = lane >> 2;   // 0..7
    const int cq   = lane & 3;    // 0..3

    const int mblk  = blockIdx.y * 128;
    const int nblk  = blockIdx.x * 128;
    const int kbase = blockIdx.z * kChunk;
    const int nk    = kChunk >> 4;

    // copy task coords
    const int aM0 = tid >> 2, aQ = tid & 3, aM1 = aM0 + 64;
    const int bK0 = tid >> 5, bQ = tid & 31, bK1 = bK0 + 8;

    const bool aP0 = (mblk + aM0) < M;
    const bool aP1 = (mblk + aM1) < M;
    const int  aR0 = aP0 ? (mblk + aM0) : 0;   // clamped row (zfill anyway)
    const int  aR1 = aP1 ? (mblk + aM1) : 0;

    const uint32_t sbase = (uint32_t)__cvta_generic_to_shared(smem);

    float acc[4][4][4];
#pragma unroll
    for (int i = 0; i < 4; ++i)
#pragma unroll
        for (int j = 0; j < 4; ++j)
#pragma unroll
            for (int k = 0; k < 4; ++k) acc[i][j][k] = 0.0f;

    // ---- issue one stage's copies ----
    auto issue = [&](int stage, int kt) {
        const int kg = kbase + kt * 16;
        const uint32_t sA = sbase + (uint32_t)(stage * STAGE_F) * 4u;
        const uint32_t sB = sA + (uint32_t)ASZ * 4u;
        cp_async16(sA + (uint32_t)(aM0 * ASTR + aQ * 4) * 4u,
                   A + (size_t)aR0 * K + kg + aQ * 4, aP0);
        cp_async16(sA + (uint32_t)(aM1 * ASTR + aQ * 4) * 4u,
                   A + (size_t)aR1 * K + kg + aQ * 4, aP1);
        cp_async16(sB + (uint32_t)(bK0 * BSTR + bQ * 4) * 4u,
                   B + (size_t)(kg + bK0) * N + nblk + bQ * 4, true);
        cp_async16(sB + (uint32_t)(bK1 * BSTR + bQ * 4) * 4u,
                   B + (size_t)(kg + bK1) * N + nblk + bQ * 4, true);
    };

    // prologue: stages 0..STAGES-2
#pragma unroll
    for (int s = 0; s < STAGES - 1; ++s) {
        if (s < nk) issue(s, s);
        cp_commit();
    }

    int fetch = STAGES - 1;
    for (int kt = 0; kt < nk; ++kt) {
        cp_wait<STAGES - 2>();
        __syncthreads();

        if (fetch < nk) issue(fetch % STAGES, fetch);
        cp_commit();
        ++fetch;

        const float* sAc = smem + (kt % STAGES) * STAGE_F;
        const float* sBc = sAc + ASZ;

#pragma unroll
        for (int ks = 0; ks < 2; ++ks) {
            const int kk = ks * 8;
            uint32_t af[4][4];
#pragma unroll
            for (int tm = 0; tm < 4; ++tm) {
                const int row0 = wm * 64 + tm * 16 + g;
                af[tm][0] = f2tf32u(sAc[row0 * ASTR       + kk + cq    ]);
                af[tm][1] = f2tf32u(sAc[(row0 + 8) * ASTR + kk + cq    ]);
                af[tm][2] = f2tf32u(sAc[row0 * ASTR       + kk + cq + 4]);
                af[tm][3] = f2tf32u(sAc[(row0 + 8) * ASTR + kk + cq + 4]);
            }
            uint32_t bf[4][2];
#pragma unroll
            for (int tn = 0; tn < 4; ++tn) {
                const int col = wn * 32 + tn * 8 + g;
                bf[tn][0] = f2tf32u(sBc[(kk + cq    ) * BSTR + col]);
                bf[tn][1] = f2tf32u(sBc[(kk + cq + 4) * BSTR + col]);
            }
#pragma unroll
            for (int tm = 0; tm < 4; ++tm)
#pragma unroll
                for (int tn = 0; tn < 4; ++tn)
                    mma_tf32(acc[tm][tn][0], acc[tm][tn][1], acc[tm][tn][2], acc[tm][tn][3],
                             af[tm][0], af[tm][1], af[tm][2], af[tm][3],
                             bf[tn][0], bf[tn][1]);
        }
        __syncthreads();
    }

    // write split-K partial slice
    const size_t zbase = (size_t)blockIdx.z * M;
#pragma unroll
    for (int tm = 0; tm < 4; ++tm) {
#pragma unroll
        for (int tn = 0; tn < 4; ++tn) {
            const int row = mblk + wm * 64 + tm * 16 + g;
            const int col = nblk + wn * 32 + tn * 8 + cq * 2;
            if (row < M) {
                C[(zbase + row) * N + col    ] = acc[tm][tn][0];
                C[(zbase + row) * N + col + 1] = acc[tm][tn][1];
            }
            if (row + 8 < M) {
                C[(zbase + row + 8) * N + col    ] = acc[tm][tn][2];
                C[(zbase + row + 8) * N + col + 1] = acc[tm][tn][3];
            }
        }
    }
}

// ---------------- split-K reduce + bias + relu ----------------
__global__ void epi_relu_kernel(const float* __restrict__ part,
                                const float* __restrict__ bias,
                                float* __restrict__ out, int MN, int N, int S) {
    const int idx = blockIdx.x * blockDim.x + threadIdx.x;
    if (idx >= MN) return;
    float v = bias[idx % N];
    for (int s = 0; s < S; ++s) v += part[(size_t)s * MN + idx];
    out[idx] = fmaxf(v, 0.0f);
}

// ---------------- head epilogue ----------------
__global__ void epi_head_kernel(const float* __restrict__ part,
                                const float* __restrict__ b_loc,
                                const float* __restrict__ b_score,
                                float* __restrict__ out, int S) {
    const int idx = blockIdx.x * blockDim.x + threadIdx.x;
    if (idx >= R_ROIS * 105) return;
    const int r = idx / 105;
    const int j = idx - r * 105;
    float v = 0.0f;
    for (int s = 0; s < S; ++s)
        v += part[((size_t)s * R_ROIS + r) * NHEAD + j];
    if (j < 84) out[r * 84 + j] = v + b_loc[j];
    else        out[R_ROIS * 84 + r * 21 + (j - 84)] = v + b_score[j - 84];
}

// ---------------- launch ----------------
extern "C" void kernel_launch(void* const* d_in, const int* in_sizes, int n_in,
                              void* d_out, int out_size) {
    const float* x    = (const float*)d_in[0];
    const float* rois = (const float*)d_in[1];
    const float* W6   = (const float*)d_in[2];
    const float* b6   = (const float*)d_in[3];
    const float* W7   = (const float*)d_in[4];
    const float* b7   = (const float*)d_in[5];
    const float* Wl   = (const float*)d_in[6];
    const float* bl   = (const float*)d_in[7];
    const float* Wsc  = (const float*)d_in[8];
    const float* bsc  = (const float*)d_in[9];
    float* out = (float*)d_out;

    float *pool, *fc6, *fc7, *part, *wh;
    cudaGetSymbolAddress((void**)&pool, g_pool);
    cudaGetSymbolAddress((void**)&fc6,  g_fc6);
    cudaGetSymbolAddress((void**)&fc7,  g_fc7);
    cudaGetSymbolAddress((void**)&part, g_part);
    cudaGetSymbolAddress((void**)&wh,   g_Whead);

    // Immediate, idempotent host API (not a stream op, not an allocation):
    // called unconditionally on every launch — no static guards.
    cudaFuncSetAttribute(gemm_tf32, cudaFuncAttributeMaxDynamicSharedMemorySize,
                         SMEM_BYTES);

    roi_pool_kernel<<<R_ROIS, 256>>>(x, rois, pool);
    pack_head_kernel<<<(NFC * NHEAD + 255) / 256, 256>>>(Wl, Wsc, wh);

    // fc6: M=300, N=4096, K=25088, split-K=4 (kChunk=6272)
    gemm_tf32<<<dim3(32, 3, 4), 256, SMEM_BYTES>>>(pool, W6, part, R_ROIS, NFC, POOLK, 6272);
    epi_relu_kernel<<<(R_ROIS * NFC + 255) / 256, 256>>>(part, b6, fc6, R_ROIS * NFC, NFC, 4);

    // fc7: M=300, N=4096, K=4096, split-K=2 (kChunk=2048)
    gemm_tf32<<<dim3(32, 3, 2), 256, SMEM_BYTES>>>(fc6, W7, part, R_ROIS, NFC, NFC, 2048);
    epi_relu_kernel<<<(R_ROIS * NFC + 255) / 256, 256>>>(part, b7, fc7, R_ROIS * NFC, NFC, 2);

    // heads: M=300, N=128 (packed), K=4096, split-K=8 (kChunk=512)
    gemm_tf32<<<dim3(1, 3, 8), 256, SMEM_BYTES>>>(fc7, wh, part, R_ROIS, NHEAD, NFC, 512);
    epi_head_kernel<<<(R_ROIS * 105 + 255) / 256, 256>>>(part, bl, bsc, out, 8);
}

// round 6
// speedup vs baseline: 1.3450x; 1.1049x over previous
#include <cuda_runtime.h>
#include <cstdint>

#define R_ROIS 300
#define CCH    512
#define HFDIM  50
#define WFDIM  50
#define POOLK  25088   // 512*7*7
#define NFC    4096
#define NHEAD  128     // padded head output cols (84 loc + 21 score + pad)

// GEMM tiling
#define STAGES 5
#define ASTR   20                 // A smem row stride (floats): 16 data + 4 pad
#define BSTR   136                // B smem row stride (floats): 128 data + 8 pad
#define ASZ    (128 * ASTR)       // 2560 floats / stage
#define BSZ    (16 * BSTR)        // 2176 floats / stage
#define STAGE_F (ASZ + BSZ)       // 4736 floats
#define SMEM_BYTES (STAGES * STAGE_F * 4)   // 94720 B

// ---------------- scratch (no allocations allowed) ----------------
__device__ __align__(16) float g_pool[R_ROIS * POOLK];
__device__ __align__(16) float g_fc6 [R_ROIS * NFC];
__device__ __align__(16) float g_fc7 [R_ROIS * NFC];
__device__ __align__(16) float g_part[4 * R_ROIS * NFC];
__device__ __align__(16) float g_Whead[NFC * NHEAD];

// ---------------- helpers ----------------
__device__ __forceinline__ uint32_t f2tf32u(float x) {
    uint32_t r;
    asm("cvt.rna.tf32.f32 %0, %1;" : "=r"(r) : "f"(x));
    return r;
}

__device__ __forceinline__ void mma_tf32(float& c0, float& c1, float& c2, float& c3,
                                         uint32_t a0, uint32_t a1, uint32_t a2, uint32_t a3,
                                         uint32_t b0, uint32_t b1) {
    asm volatile(
        "mma.sync.aligned.m16n8k8.row.col.f32.tf32.tf32.f32 "
        "{%0,%1,%2,%3}, {%4,%5,%6,%7}, {%8,%9}, {%0,%1,%2,%3};\n"
        : "+f"(c0), "+f"(c1), "+f"(c2), "+f"(c3)
        : "r"(a0), "r"(a1), "r"(a2), "r"(a3), "r"(b0), "r"(b1));
}

__device__ __forceinline__ void cp_async16(uint32_t smem, const void* gmem, bool full) {
    int sz = full ? 16 : 0;
    asm volatile("cp.async.cg.shared.global [%0], [%1], 16, %2;\n"
                 :: "r"(smem), "l"(gmem), "r"(sz));
}
__device__ __forceinline__ void cp_commit() {
    asm volatile("cp.async.commit_group;\n" ::: "memory");
}
template<int N>
__device__ __forceinline__ void cp_wait() {
    asm volatile("cp.async.wait_group %0;\n" :: "n"(N) : "memory");
}

// ---------------- no-op (launch-slot padding so ncu -s 5 hits the fc6 GEMM) ----------------
__global__ void noop_kernel() {}

// ---------------- RoI adaptive max pool ----------------
__global__ void roi_pool_kernel(const float* __restrict__ x,
                                const float* __restrict__ rois,
                                float* __restrict__ pool) {
    const int r = blockIdx.x;
    __shared__ int rs[7], re[7], cs[7], ce[7];
    if (threadIdx.x < 7) {
        const int i = threadIdx.x;
        const int y1 = (int)(rois[r * 4 + 0] * 0.0625f);
        const int x1 = (int)(rois[r * 4 + 1] * 0.0625f);
        const int y2 = (int)(rois[r * 4 + 2] * 0.0625f);
        const int x2 = (int)(rois[r * 4 + 3] * 0.0625f);
        const int h = y2 - y1 + 1;
        const int w = x2 - x1 + 1;
        rs[i] = y1 + (i * h) / 7;
        re[i] = y1 + ((i + 1) * h + 6) / 7;
        cs[i] = x1 + (i * w) / 7;
        ce[i] = x1 + ((i + 1) * w + 6) / 7;
    }
    __syncthreads();
    for (int idx = threadIdx.x; idx < CCH * 49; idx += blockDim.x) {
        const int c  = idx / 49;
        const int b  = idx - c * 49;
        const int iy = b / 7;
        const int ix = b - iy * 7;
        const float* fp = x + (size_t)c * (HFDIM * WFDIM);
        float m = -3.402823466e38f;
        const int y0 = rs[iy], y1e = re[iy];
        const int x0 = cs[ix], x1e = ce[ix];
        for (int y = y0; y < y1e; ++y) {
            const float* row = fp + y * WFDIM;
            for (int xx = x0; xx < x1e; ++xx)
                m = fmaxf(m, __ldg(row + xx));
        }
        pool[(size_t)r * POOLK + idx] = m;
    }
}

// ---------------- pack W_loc | W_score into [4096][128] ----------------
__global__ void pack_head_kernel(const float* __restrict__ Wl,
                                 const float* __restrict__ Ws,
                                 float* __restrict__ Wh) {
    const int idx = blockIdx.x * blockDim.x + threadIdx.x;
    if (idx >= NFC * NHEAD) return;
    const int k = idx >> 7;
    const int j = idx & 127;
    float v = 0.0f;
    if (j < 84)       v = Wl[k * 84 + j];
    else if (j < 105) v = Ws[k * 21 + (j - 84)];
    Wh[idx] = v;
}

// ---------------- tf32 GEMM, cp.async 5-stage pipeline, split-K ----------------
// C layout: Cpart[(z*M + row)*N + col].  BM=128, BN=128, BK=16, 256 threads.
// kChunk need not divide K evenly; the last z-slice takes the remainder
// (must remain a multiple of 16).
__global__ void __launch_bounds__(256, 2)
gemm_tf32(const float* __restrict__ A, const float* __restrict__ B,
          float* __restrict__ C, int M, int N, int K, int kChunk) {
    extern __shared__ float smem[];

    const int tid  = threadIdx.x;
    const int lane = tid & 31;
    const int warp = tid >> 5;
    const int wm   = warp >> 2;   // 0..1
    const int wn   = warp & 3;    // 0..3
    const int g    = lane >> 2;   // 0..7
    const int cq   = lane & 3;    // 0..3

    const int mblk  = blockIdx.y * 128;
    const int nblk  = blockIdx.x * 128;
    const int kbase = blockIdx.z * kChunk;
    const int kLen  = min(kChunk, K - kbase);
    const int nk    = kLen >> 4;

    // copy task coords
    const int aM0 = tid >> 2, aQ = tid & 3, aM1 = aM0 + 64;
    const int bK0 = tid >> 5, bQ = tid & 31, bK1 = bK0 + 8;

    const bool aP0 = (mblk + aM0) < M;
    const bool aP1 = (mblk + aM1) < M;
    const int  aR0 = aP0 ? (mblk + aM0) : 0;   // clamped row (zfill anyway)
    const int  aR1 = aP1 ? (mblk + aM1) : 0;

    const uint32_t sbase = (uint32_t)__cvta_generic_to_shared(smem);

    float acc[4][4][4];
#pragma unroll
    for (int i = 0; i < 4; ++i)
#pragma unroll
        for (int j = 0; j < 4; ++j)
#pragma unroll
            for (int k = 0; k < 4; ++k) acc[i][j][k] = 0.0f;

    // ---- issue one stage's copies ----
    auto issue = [&](int stage, int kt) {
        const int kg = kbase + kt * 16;
        const uint32_t sA = sbase + (uint32_t)(stage * STAGE_F) * 4u;
        const uint32_t sB = sA + (uint32_t)ASZ * 4u;
        cp_async16(sA + (uint32_t)(aM0 * ASTR + aQ * 4) * 4u,
                   A + (size_t)aR0 * K + kg + aQ * 4, aP0);
        cp_async16(sA + (uint32_t)(aM1 * ASTR + aQ * 4) * 4u,
                   A + (size_t)aR1 * K + kg + aQ * 4, aP1);
        cp_async16(sB + (uint32_t)(bK0 * BSTR + bQ * 4) * 4u,
                   B + (size_t)(kg + bK0) * N + nblk + bQ * 4, true);
        cp_async16(sB + (uint32_t)(bK1 * BSTR + bQ * 4) * 4u,
                   B + (size_t)(kg + bK1) * N + nblk + bQ * 4, true);
    };

    // prologue: stages 0..STAGES-2
#pragma unroll
    for (int s = 0; s < STAGES - 1; ++s) {
        if (s < nk) issue(s, s);
        cp_commit();
    }

    int fetch = STAGES - 1;
    for (int kt = 0; kt < nk; ++kt) {
        cp_wait<STAGES - 2>();
        __syncthreads();   // single barrier per iteration: orders stage reuse
                           // (writer stage (kt+S-1)%S == reader stage (kt-1)%S)

        if (fetch < nk) issue(fetch % STAGES, fetch);
        cp_commit();
        ++fetch;

        const float* sAc = smem + (kt % STAGES) * STAGE_F;
        const float* sBc = sAc + ASZ;

#pragma unroll
        for (int ks = 0; ks < 2; ++ks) {
            const int kk = ks * 8;
            uint32_t af[4][4];
#pragma unroll
            for (int tm = 0; tm < 4; ++tm) {
                const int row0 = wm * 64 + tm * 16 + g;
                af[tm][0] = f2tf32u(sAc[row0 * ASTR       + kk + cq    ]);
                af[tm][1] = f2tf32u(sAc[(row0 + 8) * ASTR + kk + cq    ]);
                af[tm][2] = f2tf32u(sAc[row0 * ASTR       + kk + cq + 4]);
                af[tm][3] = f2tf32u(sAc[(row0 + 8) * ASTR + kk + cq + 4]);
            }
            uint32_t bf[4][2];
#pragma unroll
            for (int tn = 0; tn < 4; ++tn) {
                const int col = wn * 32 + tn * 8 + g;
                bf[tn][0] = f2tf32u(sBc[(kk + cq    ) * BSTR + col]);
                bf[tn][1] = f2tf32u(sBc[(kk + cq + 4) * BSTR + col]);
            }
#pragma unroll
            for (int tm = 0; tm < 4; ++tm)
#pragma unroll
                for (int tn = 0; tn < 4; ++tn)
                    mma_tf32(acc[tm][tn][0], acc[tm][tn][1], acc[tm][tn][2], acc[tm][tn][3],
                             af[tm][0], af[tm][1], af[tm][2], af[tm][3],
                             bf[tn][0], bf[tn][1]);
        }
    }

    // write split-K partial slice
    const size_t zbase = (size_t)blockIdx.z * M;
#pragma unroll
    for (int tm = 0; tm < 4; ++tm) {
#pragma unroll
        for (int tn = 0; tn < 4; ++tn) {
            const int row = mblk + wm * 64 + tm * 16 + g;
            const int col = nblk + wn * 32 + tn * 8 + cq * 2;
            if (row < M) {
                C[(zbase + row) * N + col    ] = acc[tm][tn][0];
                C[(zbase + row) * N + col + 1] = acc[tm][tn][1];
            }
            if (row + 8 < M) {
                C[(zbase + row + 8) * N + col    ] = acc[tm][tn][2];
                C[(zbase + row + 8) * N + col + 1] = acc[tm][tn][3];
            }
        }
    }
}

// ---------------- split-K reduce + bias + relu ----------------
__global__ void epi_relu_kernel(const float* __restrict__ part,
                                const float* __restrict__ bias,
                                float* __restrict__ out, int MN, int N, int S) {
    const int idx = blockIdx.x * blockDim.x + threadIdx.x;
    if (idx >= MN) return;
    float v = bias[idx % N];
    for (int s = 0; s < S; ++s) v += part[(size_t)s * MN + idx];
    out[idx] = fmaxf(v, 0.0f);
}

// ---------------- head epilogue ----------------
__global__ void epi_head_kernel(const float* __restrict__ part,
                                const float* __restrict__ b_loc,
                                const float* __restrict__ b_score,
                                float* __restrict__ out, int S) {
    const int idx = blockIdx.x * blockDim.x + threadIdx.x;
    if (idx >= R_ROIS * 105) return;
    const int r = idx / 105;
    const int j = idx - r * 105;
    float v = 0.0f;
    for (int s = 0; s < S; ++s)
        v += part[((size_t)s * R_ROIS + r) * NHEAD + j];
    if (j < 84) out[r * 84 + j] = v + b_loc[j];
    else        out[R_ROIS * 84 + r * 21 + (j - 84)] = v + b_score[j - 84];
}

// ---------------- launch ----------------
extern "C" void kernel_launch(void* const* d_in, const int* in_sizes, int n_in,
                              void* d_out, int out_size) {
    const float* x    = (const float*)d_in[0];
    const float* rois = (const float*)d_in[1];
    const float* W6   = (const float*)d_in[2];
    const float* b6   = (const float*)d_in[3];
    const float* W7   = (const float*)d_in[4];
    const float* b7   = (const float*)d_in[5];
    const float* Wl   = (const float*)d_in[6];
    const float* bl   = (const float*)d_in[7];
    const float* Wsc  = (const float*)d_in[8];
    const float* bsc  = (const float*)d_in[9];
    float* out = (float*)d_out;

    float *pool, *fc6, *fc7, *part, *wh;
    cudaGetSymbolAddress((void**)&pool, g_pool);
    cudaGetSymbolAddress((void**)&fc6,  g_fc6);
    cudaGetSymbolAddress((void**)&fc7,  g_fc7);
    cudaGetSymbolAddress((void**)&part, g_part);
    cudaGetSymbolAddress((void**)&wh,   g_Whead);

    cudaFuncSetAttribute(gemm_tf32, cudaFuncAttributeMaxDynamicSharedMemorySize,
                         SMEM_BYTES);

    // launches 0-4 (noops pad so the fc6 GEMM is launch #5 for ncu -s 5 -c 1)
    roi_pool_kernel<<<R_ROIS, 256>>>(x, rois, pool);
    pack_head_kernel<<<(NFC * NHEAD + 255) / 256, 256>>>(Wl, Wsc, wh);
    noop_kernel<<<1, 32>>>();
    noop_kernel<<<1, 32>>>();
    noop_kernel<<<1, 32>>>();

    // fc6: M=300, N=4096, K=25088, split-K=3 (kChunk=8368; last slice 8352)
    // grid = 32*3*3 = 288 CTAs -> exactly one wave at occupancy 2
    gemm_tf32<<<dim3(32, 3, 3), 256, SMEM_BYTES>>>(pool, W6, part, R_ROIS, NFC, POOLK, 8368);
    epi_relu_kernel<<<(R_ROIS * NFC + 255) / 256, 256>>>(part, b6, fc6, R_ROIS * NFC, NFC, 3);

    // fc7: M=300, N=4096, K=4096, split-K=3 (kChunk=1376; last slice 1344)
    gemm_tf32<<<dim3(32, 3, 3), 256, SMEM_BYTES>>>(fc6, W7, part, R_ROIS, NFC, NFC, 1376);
    epi_relu_kernel<<<(R_ROIS * NFC + 255) / 256, 256>>>(part, b7, fc7, R_ROIS * NFC, NFC, 3);

    // heads: M=300, N=128 (packed), K=4096, split-K=8 (kChunk=512)
    gemm_tf32<<<dim3(1, 3, 8), 256, SMEM_BYTES>>>(fc7, wh, part, R_ROIS, NHEAD, NFC, 512);
    epi_head_kernel<<<(R_ROIS * 105 + 255) / 256, 256>>>(part, bl, bsc, out, 8);
}